// round 15
// baseline (speedup 1.0000x reference)
#include <cuda_runtime.h>

// Fixed problem shape
#define NB 8
#define IC 16
#define OC 32
#define H  128
#define W  128
#define HP 130
#define TH 2      // output rows per CTA
#define TW 64     // output cols per CTA

typedef unsigned long long ull;

// Packed coefficient table: [j][cg][il][k] = (cos th, -sin th)
// cg = channel group (i>>3), il = i&7, k tight: 16*4*8*3 ull = 12 KB
__device__ ull g_coef[IC * OC * 3];

// Packed (cos S, sin S): [n*IC][HP][W], 17 MB
__device__ ull g_cs[NB * IC * HP * W];

__device__ __forceinline__ void ffma2(ull& d, ull a, ull b) {
    asm("fma.rn.f32x2 %0, %1, %2, %0;" : "+l"(d) : "l"(a), "l"(b));
}

__device__ __forceinline__ ull pack2(float lo, float hi) {
    return (ull)__float_as_uint(lo) | ((ull)__float_as_uint(hi) << 32);
}

// ---------------- Kernel 1: coef + cs tensor, division-free ----------------
// grid (65, 128): blockIdx.y = nj, blockIdx.x covers HP*W/256 = 65 blocks.
__global__ __launch_bounds__(256)
void prep_kernel(const float* __restrict__ x, const float* __restrict__ theta) {
    const int tid = threadIdx.x;

    if (blockIdx.y == 0 && blockIdx.x < 8) {
        int t = blockIdx.x * 256 + tid;          // < 2048 (k padded to 4)
        int j = t >> 7;
        int i = (t >> 2) & 31;
        int k = t & 3;
        if (k < 3) {
            float s, c;
            sincosf(theta[(i * j) * 3 + k], &s, &c);
            g_coef[j * 96 + (i >> 3) * 24 + (i & 7) * 3 + k] = pack2(c, -s);
        }
    }

    const int nj   = blockIdx.y;
    const int q    = blockIdx.x * 256 + tid;     // < HP*W
    const int w    = q & 127;
    const int hp   = q >> 7;
    const int lane = tid & 31;

    ull outv;
    int gr = hp - 1;
    if ((unsigned)gr < (unsigned)H) {
        const float* xr = x + ((size_t)nj * H + gr) * W;
        float v  = xr[w];
        float vm = __shfl_up_sync(0xffffffffu, v, 1);
        if (lane == 0)  vm = (w > 0)   ? xr[w - 1] : 0.f;
        float vp = __shfl_down_sync(0xffffffffu, v, 1);
        if (lane == 31) vp = (w < 127) ? xr[w + 1] : 0.f;
        float S = vm + v + vp;
        float s, c;
        __sincosf(S, &s, &c);
        outv = pack2(c, s);
    } else {
        outv = pack2(1.f, 0.f);   // S = 0 on pad rows
    }
    g_cs[(size_t)nj * (HP * W) + q] = outv;
}

// ---------------- Kernel 2: contraction, channel-major threads --------------
// grid (2, 64, 8) = 1024 CTAs. 8 warps; warp ig: column half = ig&1 (32 cols),
// channel group cg = ig>>1 (8 channels). Thread owns ONE column w0, rows
// {h0, h0+1}, 8 channels: acc = 16 ull. Data = 4 LDS.64/j (half the bytes of
// the 2-col layout); coef = 12 broadcast LDS.128/j.
__global__ __launch_bounds__(256, 3)
void contract_kernel(float* __restrict__ out) {
    __shared__ __align__(16) ull sCS[IC * (TH + 2) * TW];  // 32 KB
    __shared__ __align__(16) ull sCoef[IC * OC * 3];       // 12 KB

    const int tid  = threadIdx.x;
    const int lane = tid & 31;
    const int ig   = tid >> 5;
    const int cg   = ig >> 1;           // channel group: channels 8*cg..8*cg+7
    const int w0   = (ig & 1) * 32 + lane;
    const int tw   = blockIdx.x;
    const int h0   = blockIdx.y * TH;
    const int n    = blockIdx.z;

    // Stage coef table: 768 float4, 3 per thread
    {
        const float4* src = reinterpret_cast<const float4*>(g_coef);
        float4* dst = reinterpret_cast<float4*>(sCoef);
        #pragma unroll
        for (int r = 0; r < 3; ++r)
            dst[tid + 256 * r] = src[tid + 256 * r];
    }

    // Stage CS slab: 16 j x 4 rows x 64 cols = 2048 ulonglong2 (8/thread)
    {
        const ull* gsrc = g_cs + ((size_t)n * IC * HP + h0) * W + tw * TW;
        #pragma unroll
        for (int it = 0; it < 8; ++it) {
            int q   = it * 256 + tid;     // 0..2047
            int c2  = q & 31;             // ulonglong2 within row
            int row = q >> 5;             // 0..63
            int r   = row & 3;
            int j   = row >> 2;
            ulonglong2 v = *reinterpret_cast<const ulonglong2*>(
                gsrc + ((size_t)j * HP + r) * W + 2 * c2);
            *reinterpret_cast<ulonglong2*>(sCS + (j * 4 + r) * TW + 2 * c2) = v;
        }
    }
    __syncthreads();   // the only barrier

    // acc[il][r]: il = channel-in-group (8), r = output row (2)
    ull acc[8][2];
    #pragma unroll
    for (int il = 0; il < 8; ++il) {
        acc[il][0] = 0ull;
        acc[il][1] = 0ull;
    }

    const ull* coefBase = sCoef + cg * 24;

    #pragma unroll 1
    for (int jx = 0; jx < IC; ++jx) {
        const int j = (jx + 2 * ig) & 15;        // per-warp rotation

        const ull* base = sCS + j * 4 * TW + w0;
        ull e0 = base[0 * TW];
        ull e1 = base[1 * TW];
        ull e2 = base[2 * TW];
        ull e3 = base[3 * TW];

        const ull* cfb = coefBase + j * 96;
        #pragma unroll
        for (int ilp = 0; ilp < 4; ++ilp) {
            // 6 coef pairs = 2 channels: 3 broadcast LDS.128
            ulonglong2 p0 = *reinterpret_cast<const ulonglong2*>(cfb + ilp * 6);
            ulonglong2 p1 = *reinterpret_cast<const ulonglong2*>(cfb + ilp * 6 + 2);
            ulonglong2 p2 = *reinterpret_cast<const ulonglong2*>(cfb + ilp * 6 + 4);
            const int a = 2 * ilp, b = 2 * ilp + 1;
            // channel a: c0=p0.x c1=p0.y c2=p1.x
            ffma2(acc[a][0], e0, p0.x);
            ffma2(acc[a][0], e1, p0.y);
            ffma2(acc[a][0], e2, p1.x);
            ffma2(acc[a][1], e1, p0.x);
            ffma2(acc[a][1], e2, p0.y);
            ffma2(acc[a][1], e3, p1.x);
            // channel b: c0=p1.y c1=p2.x c2=p2.y
            ffma2(acc[b][0], e0, p1.y);
            ffma2(acc[b][0], e1, p2.x);
            ffma2(acc[b][0], e2, p2.y);
            ffma2(acc[b][1], e1, p1.y);
            ffma2(acc[b][1], e2, p2.x);
            ffma2(acc[b][1], e3, p2.y);
        }
    }

    // Epilogue: out = (lo + hi) / 3, STG.32 (lane-coalesced)
    #pragma unroll
    for (int il = 0; il < 8; ++il) {
        const int ch = cg * 8 + il;
        float* op = out + ((size_t)(n * OC + ch) * H + h0) * W + tw * TW + w0;
        #pragma unroll
        for (int r = 0; r < 2; ++r) {
            ull a = acc[il][r];
            op[(size_t)r * W] =
                (__uint_as_float((unsigned)(a & 0xffffffffu)) +
                 __uint_as_float((unsigned)(a >> 32))) * (1.0f / 3.0f);
        }
    }
}

extern "C" void kernel_launch(void* const* d_in, const int* in_sizes, int n_in,
                              void* d_out, int out_size) {
    const float* x     = (const float*)d_in[0];   // (8,16,128,128) f32
    const float* theta = (const float*)d_in[1];   // (1536,3) f32
    float* out = (float*)d_out;                   // (8,32,128,128) f32

    dim3 pgrid(HP * W / 256, NB * IC);            // (65, 128)
    prep_kernel<<<pgrid, 256>>>(x, theta);

    dim3 grid(W / TW, H / TH, NB);                // 1024 CTAs
    contract_kernel<<<grid, 256>>>(out);
}